// round 15
// baseline (speedup 1.0000x reference)
#include <cuda_runtime.h>
#include <cuda_bf16.h>
#include <cuda_fp16.h>
#include <math.h>
#include <stdint.h>

#define DIM 1024
#define BSZ 4
#define SEQ 1024
#define NH 16
#define HD 64
#define MTOT (BSZ*SEQ)

typedef unsigned short ush;

// ---------------------------------------------------------------------------
// Scratch (device globals, no allocations).  All fp16.
// ---------------------------------------------------------------------------
__device__ ush g_xh[MTOT*DIM], g_xl[MTOT*DIM];     // x split
__device__ ush g_qh[MTOT*DIM], g_ql[MTOT*DIM];     // Q split (rotated)
__device__ ush g_kh[MTOT*DIM];                     // K fp16 (rotated)
__device__ ush g_vh[MTOT*DIM];                     // V fp16
__device__ ush g_ah[MTOT*DIM], g_al[MTOT*DIM];     // attn-out split
__device__ ush g_wqh[DIM*DIM];                     // weights fp16 (hi only)
__device__ ush g_wkh[DIM*DIM];
__device__ ush g_wvh[DIM*DIM];
__device__ ush g_woh[DIM*DIM];

// ---------------------------------------------------------------------------
// Helpers
// ---------------------------------------------------------------------------
__device__ __forceinline__ uint32_t smem_u32(const void* p) {
    uint32_t a;
    asm("{ .reg .u64 t; cvta.to.shared.u64 t, %1; cvt.u32.u64 %0, t; }" : "=r"(a) : "l"(p));
    return a;
}

__device__ __forceinline__ void ldsm4(uint32_t* r, uint32_t addr) {
    asm volatile("ldmatrix.sync.aligned.m8n8.x4.shared.b16 {%0,%1,%2,%3}, [%4];"
                 : "=r"(r[0]), "=r"(r[1]), "=r"(r[2]), "=r"(r[3]) : "r"(addr));
}
__device__ __forceinline__ void ldsm4t(uint32_t* r, uint32_t addr) {
    asm volatile("ldmatrix.sync.aligned.m8n8.x4.trans.shared.b16 {%0,%1,%2,%3}, [%4];"
                 : "=r"(r[0]), "=r"(r[1]), "=r"(r[2]), "=r"(r[3]) : "r"(addr));
}

// fp16 in, f32 accum
__device__ __forceinline__ void mma_h(float* c, const uint32_t* a, const uint32_t* b) {
    asm volatile(
        "mma.sync.aligned.m16n8k16.row.col.f32.f16.f16.f32 "
        "{%0,%1,%2,%3}, {%4,%5,%6,%7}, {%8,%9}, {%0,%1,%2,%3};\n"
        : "+f"(c[0]), "+f"(c[1]), "+f"(c[2]), "+f"(c[3])
        : "r"(a[0]), "r"(a[1]), "r"(a[2]), "r"(a[3]), "r"(b[0]), "r"(b[1]));
}

__device__ __forceinline__ void cp16(uint32_t saddr, const void* g) {
    asm volatile("cp.async.cg.shared.global [%0], [%1], 16;" :: "r"(saddr), "l"(g));
}
#define CP_COMMIT() asm volatile("cp.async.commit_group;" ::: "memory")
#define CP_WAIT(n)  asm volatile("cp.async.wait_group %0;" :: "n"(n) : "memory")

// fp16 packers
__device__ __forceinline__ uint32_t packh_hi(float c0, float c1) {
    __half2 h = __floats2half2_rn(c0, c1);
    return *(uint32_t*)&h;
}
__device__ __forceinline__ uint32_t packh_lo(float c0, float c1, uint32_t hibits) {
    __half2 h = *(__half2*)&hibits;
    __half2 r = __floats2half2_rn(c0 - __half2float(__low2half(h)),
                                  c1 - __half2float(__high2half(h)));
    return *(uint32_t*)&r;
}

// ---------------------------------------------------------------------------
// Merged split kernel: x -> fp16 (hi,lo); weights -> fp16 hi only
// ---------------------------------------------------------------------------
#define N4X (MTOT*DIM/4)
#define N4W (DIM*DIM/4)

__global__ void split_all(const float* __restrict__ x,
                          const float* __restrict__ wq, const float* __restrict__ wk,
                          const float* __restrict__ wv, const float* __restrict__ wo,
                          ush* __restrict__ xh, ush* __restrict__ xl,
                          ush* __restrict__ wqh, ush* __restrict__ wkh,
                          ush* __restrict__ wvh, ush* __restrict__ woh)
{
    int i = blockIdx.x * blockDim.x + threadIdx.x;
    const float* src; ush* hi; ush* lo = nullptr; int j;
    if (i < N4X)            { src = x;  hi = xh;  lo = xl; j = i; }
    else if (i < N4X+N4W)   { src = wq; hi = wqh; j = i - N4X; }
    else if (i < N4X+2*N4W) { src = wk; hi = wkh; j = i - N4X - N4W; }
    else if (i < N4X+3*N4W) { src = wv; hi = wvh; j = i - N4X - 2*N4W; }
    else if (i < N4X+4*N4W) { src = wo; hi = woh; j = i - N4X - 3*N4W; }
    else return;

    float4 v = ((const float4*)src)[j];
    float vv[4] = {v.x, v.y, v.z, v.w};
    ush h[4];
#pragma unroll
    for (int q = 0; q < 4; q++) h[q] = __half_as_ushort(__float2half_rn(vv[q]));
    ((uint2*)hi)[j] = make_uint2((uint32_t)h[0] | ((uint32_t)h[1] << 16),
                                 (uint32_t)h[2] | ((uint32_t)h[3] << 16));
    if (lo) {
        ush l[4];
#pragma unroll
        for (int q = 0; q < 4; q++)
            l[q] = __half_as_ushort(__float2half_rn(vv[q] - __half2float(__ushort_as_half(h[q]))));
        ((uint2*)lo)[j] = make_uint2((uint32_t)l[0] | ((uint32_t)l[1] << 16),
                                     (uint32_t)l[2] | ((uint32_t)l[3] << 16));
    }
}

// ---------------------------------------------------------------------------
// HMMA GEMM, 2-pass fp16: CTA 128x128, BK=64, 128 thr / 4 warps (2x2),
// warp tile 64x64, 2 CTAs/SM. 12 LDSM feed 64 HMMA per k16 window.
// OUTMODE 1: fp32+bias (O).  OUTMODE 3: fused QKV epilogue.
// ---------------------------------------------------------------------------
#define GBM 128
#define GBN 128
#define GBK 64
#define GST 72                        // smem row stride (elems) = 144 B
#define TBUF (128*GST*2)              // 18432 B
#define GSTG (3*TBUF)                 // Ah, Al, Bh = 55296 B
#define GEMM_SMEM (2*GSTG)            // 110592 B -> 2 CTAs/SM
#define GNKB (DIM/GBK)                // 16
#define GNT 128                       // threads

template<int OUTMODE>
__global__ void __launch_bounds__(GNT, 2)
gemm_fused(const ush* __restrict__ Ah, const ush* __restrict__ Al,
           const ush* __restrict__ B0h, const ush* __restrict__ B1h,
           const ush* __restrict__ B2h,
           const float* __restrict__ bias, float* __restrict__ C,
           ush* __restrict__ Qh_, ush* __restrict__ Ql_,
           ush* __restrict__ Kh_, ush* __restrict__ Vh_)
{
    extern __shared__ char smc[];
    uint32_t sbase = smem_u32(smc);
    int tid  = threadIdx.x;
    int wid  = tid >> 5, lane = tid & 31;
    int wm   = wid >> 1;               // 0..1  (64-row half)
    int wn   = wid & 1;                // 0..1  (64-col half)
    int m0   = blockIdx.y * GBM;
    int n0g  = blockIdx.x * GBN;

    const ush* gBh;
    if (OUTMODE == 3) {
        int mat  = n0g >> 10;
        int nloc = n0g & 1023;
        gBh = (mat == 0 ? B0h : mat == 1 ? B1h : B2h) + (size_t)nloc * DIM;
    } else {
        gBh = B0h + (size_t)n0g * DIM;
    }
    const ush* gAh = Ah + (size_t)m0 * DIM;
    const ush* gAl = Al + (size_t)m0 * DIM;

    auto load_stage = [&](int p, int kb) {
        uint32_t sb = sbase + p * GSTG;
        // 128 rows x 8 chunks(16B) = 1024 chunks per matrix, 8 per thread
#pragma unroll
        for (int r = 0; r < 8; r++) {
            int c = tid + GNT * r;
            int row = c >> 3, ch = c & 7;
            uint32_t so = (uint32_t)(row * GST + ch * 8) * 2;
            size_t go = (size_t)row * DIM + kb * GBK + ch * 8;
            cp16(sb + so,            gAh + go);
            cp16(sb + TBUF + so,     gAl + go);
            cp16(sb + 2 * TBUF + so, gBh + go);
        }
    };

    float acc[4][8][4];
#pragma unroll
    for (int i = 0; i < 4; i++)
#pragma unroll
        for (int j = 0; j < 8; j++)
#pragma unroll
            for (int q = 0; q < 4; q++) acc[i][j][q] = 0.0f;

    int a_row_lane = lane & 15;
    int a_hi8      = lane >> 4;
    int b_row_lane = (lane & 7) + ((lane & 16) ? 8 : 0);
    int b_hi8      = (lane >> 3) & 1;

    load_stage(0, 0); CP_COMMIT();

    for (int kb = 0; kb < GNKB; kb++) {
        if (kb + 1 < GNKB) { load_stage((kb + 1) & 1, kb + 1); CP_COMMIT(); CP_WAIT(1); }
        else CP_WAIT(0);
        __syncthreads();

        uint32_t sb  = sbase + (kb & 1) * GSTG;
        uint32_t sAh = sb, sAl = sb + TBUF, sBh = sb + 2 * TBUF;

#pragma unroll
        for (int ks = 0; ks < 4; ks++) {
            uint32_t aH[4][4], aL[4][4], b4[4][4];
#pragma unroll
            for (int mt = 0; mt < 4; mt++) {
                int row = wm * 64 + mt * 16 + a_row_lane;
                uint32_t off = (uint32_t)(row * GST + ks * 16 + a_hi8 * 8) * 2;
                ldsm4(aH[mt], sAh + off);
                ldsm4(aL[mt], sAl + off);
            }
#pragma unroll
            for (int ng = 0; ng < 4; ng++) {
                int row = wn * 64 + ng * 16 + b_row_lane;
                uint32_t off = (uint32_t)(row * GST + ks * 16 + b_hi8 * 8) * 2;
                ldsm4(b4[ng], sBh + off);
            }
            // pass H: 32 consecutive MMAs on distinct accumulators
#pragma unroll
            for (int ng = 0; ng < 4; ng++)
#pragma unroll
                for (int mt = 0; mt < 4; mt++) {
                    mma_h(acc[mt][2*ng],   aH[mt], b4[ng]);
                    mma_h(acc[mt][2*ng+1], aH[mt], b4[ng] + 2);
                }
            // pass L
#pragma unroll
            for (int ng = 0; ng < 4; ng++)
#pragma unroll
                for (int mt = 0; mt < 4; mt++) {
                    mma_h(acc[mt][2*ng],   aL[mt], b4[ng]);
                    mma_h(acc[mt][2*ng+1], aL[mt], b4[ng] + 2);
                }
        }
        __syncthreads();
    }

    // ---- epilogue ----
#pragma unroll
    for (int mt = 0; mt < 4; mt++) {
        int row = m0 + wm * 64 + mt * 16 + (lane >> 2);
#pragma unroll
        for (int nt = 0; nt < 8; nt++) {
            int col = n0g + wn * 64 + nt * 8 + (lane & 3) * 2;
            float2 v0 = make_float2(acc[mt][nt][0], acc[mt][nt][1]);
            float2 v1 = make_float2(acc[mt][nt][2], acc[mt][nt][3]);
            if (OUTMODE == 1) {
                v0.x += bias[col]; v0.y += bias[col + 1];
                v1.x += bias[col]; v1.y += bias[col + 1];
                *(float2*)&C[(size_t)row * DIM + col] = v0;
                *(float2*)&C[(size_t)(row + 8) * DIM + col] = v1;
            } else {
                int mat  = col >> 10;
                int nloc = col & 1023;
                size_t d0 = (size_t)row * DIM + nloc;
                size_t d1 = d0 + (size_t)8 * DIM;
                if (mat == 2) {
                    *(uint32_t*)&Vh_[d0] = packh_hi(v0.x, v0.y);
                    *(uint32_t*)&Vh_[d1] = packh_hi(v1.x, v1.y);
                } else {
                    int s = row & (SEQ - 1);
                    float ex = (float)nloc * (1.0f / (float)DIM);
                    float freq = powf(10000.0f, -ex);
                    float sn0, cs0, sn1, cs1;
                    sincosf((float)s * freq, &sn0, &cs0);
                    sincosf((float)(s + 8) * freq, &sn1, &cs1);
                    float r0x = v0.x * cs0 - v0.y * sn0;
                    float r0y = v0.x * sn0 + v0.y * cs0;
                    float r1x = v1.x * cs1 - v1.y * sn1;
                    float r1y = v1.x * sn1 + v1.y * cs1;
                    if (mat == 0) {
                        uint32_t h0 = packh_hi(r0x, r0y);
                        uint32_t h1 = packh_hi(r1x, r1y);
                        *(uint32_t*)&Qh_[d0] = h0;
                        *(uint32_t*)&Ql_[d0] = packh_lo(r0x, r0y, h0);
                        *(uint32_t*)&Qh_[d1] = h1;
                        *(uint32_t*)&Ql_[d1] = packh_lo(r1x, r1y, h1);
                    } else {
                        *(uint32_t*)&Kh_[d0] = packh_hi(r0x, r0y);
                        *(uint32_t*)&Kh_[d1] = packh_hi(r1x, r1y);
                    }
                }
            }
        }
    }
}

// ---------------------------------------------------------------------------
// Flash attention, fp16 2-pass. 64 q-rows/CTA, 128 threads / 4 warps,
// key tiles of 128, 2 CTAs/SM (smem 92160 B). Unchanged from R13.
// ---------------------------------------------------------------------------
#define FROWB 144
#define FQT (64*FROWB)
#define FKT (128*FROWB)
#define FKV0 (2*FQT)
#define FSTG (2*FKT)
#define FLASH_SMEM (2*FQT + 2*FSTG)
#define NKT (SEQ/128)
#define FNT 128

__global__ void __launch_bounds__(FNT, 2)
flash_mma(const ush* __restrict__ Qh, const ush* __restrict__ Ql,
          const ush* __restrict__ Kh, const ush* __restrict__ Vh,
          ush* __restrict__ Oh, ush* __restrict__ Ol)
{
    extern __shared__ char smf[];
    uint32_t sbase = smem_u32(smf);
    int tid = threadIdx.x;
    int wid = tid >> 5, lane = tid & 31;
    int b = blockIdx.z, h = blockIdx.y;
    int q0 = blockIdx.x * 64;

    size_t qrow0 = (size_t)(b * SEQ + q0);
    size_t krow0 = (size_t)(b * SEQ);
    int hc = h * HD;

    {
#pragma unroll
        for (int i = 0; i < 4; i++) {
            int c = tid + i * FNT;
            int row = c >> 3, ch = c & 7;
            uint32_t so = sbase + row * FROWB + ch * 16;
            size_t go = (qrow0 + row) * DIM + hc + ch * 8;
            cp16(so, Qh + go);
            cp16(so + FQT, Ql + go);
        }
        CP_COMMIT();
    }

    auto load_kv = [&](int t) {
        uint32_t sb = sbase + FKV0 + (t & 1) * FSTG;
        size_t rbase = (krow0 + (size_t)t * 128) * DIM + hc;
#pragma unroll
        for (int i = 0; i < 8; i++) {
            int c = tid + i * FNT;
            int row = c >> 3, ch = c & 7;
            uint32_t so = sb + row * FROWB + ch * 16;
            size_t go = rbase + (size_t)row * DIM + ch * 8;
            cp16(so,       Kh + go);
            cp16(so + FKT, Vh + go);
        }
        CP_COMMIT();
    };

    load_kv(0);

    float out[8][4];
#pragma unroll
    for (int i = 0; i < 8; i++)
#pragma unroll
        for (int j = 0; j < 4; j++) out[i][j] = 0.0f;
    float m2[2] = {-1e30f, -1e30f};
    float lsum[2] = {0.0f, 0.0f};

    uint32_t aQh[4][4], aQl[4][4];
    const float C2 = 0.18033688f;

    int a_row_lane = lane & 15;
    int a_hi8      = lane >> 4;
    int b_row_lane = (lane & 7) + ((lane & 16) ? 8 : 0);
    int b_hi8      = (lane >> 3) & 1;
    int v_krel = (lane & 7) + ((lane & 8) ? 8 : 0);
    int v_chi  = (lane & 16) ? 8 : 0;

    for (int t = 0; t < NKT; t++) {
        if (t + 1 < NKT) { load_kv(t + 1); CP_WAIT(1); }
        else CP_WAIT(0);
        __syncthreads();

        if (t == 0) {
#pragma unroll
            for (int kk = 0; kk < 4; kk++) {
                int row = wid * 16 + a_row_lane;
                uint32_t off = sbase + row * FROWB + (kk * 16 + a_hi8 * 8) * 2;
                ldsm4(aQh[kk], off);
                ldsm4(aQl[kk], off + FQT);
            }
        }

        uint32_t sK = sbase + FKV0 + (t & 1) * FSTG;
        uint32_t sV = sK + FKT;

        float acc[16][4];
#pragma unroll
        for (int i = 0; i < 16; i++)
#pragma unroll
            for (int j = 0; j < 4; j++) acc[i][j] = 0.0f;

#pragma unroll
        for (int kk = 0; kk < 4; kk++) {
#pragma unroll
            for (int ntp = 0; ntp < 8; ntp++) {
                int row = ntp * 16 + b_row_lane;
                uint32_t off = row * FROWB + (kk * 16 + b_hi8 * 8) * 2;
                uint32_t bh4[4];
                ldsm4(bh4, sK + off);
                mma_h(acc[2*ntp],   aQh[kk], bh4);
                mma_h(acc[2*ntp+1], aQh[kk], bh4 + 2);
                mma_h(acc[2*ntp],   aQl[kk], bh4);
                mma_h(acc[2*ntp+1], aQl[kk], bh4 + 2);
            }
        }

        float lm0 = -1e30f, lm1 = -1e30f;
#pragma unroll
        for (int nt = 0; nt < 16; nt++) {
            lm0 = fmaxf(lm0, fmaxf(acc[nt][0], acc[nt][1]));
            lm1 = fmaxf(lm1, fmaxf(acc[nt][2], acc[nt][3]));
        }
        lm0 = fmaxf(lm0, __shfl_xor_sync(0xffffffffu, lm0, 1));
        lm0 = fmaxf(lm0, __shfl_xor_sync(0xffffffffu, lm0, 2));
        lm1 = fmaxf(lm1, __shfl_xor_sync(0xffffffffu, lm1, 1));
        lm1 = fmaxf(lm1, __shfl_xor_sync(0xffffffffu, lm1, 2));
        float nm0 = fmaxf(m2[0], lm0 * C2);
        float nm1 = fmaxf(m2[1], lm1 * C2);
        float sc0 = exp2f(m2[0] - nm0);
        float sc1 = exp2f(m2[1] - nm1);
        m2[0] = nm0; m2[1] = nm1;

        float rs0 = 0.0f, rs1 = 0.0f;
#pragma unroll
        for (int nt = 0; nt < 16; nt++) {
            acc[nt][0] = exp2f(acc[nt][0] * C2 - nm0);
            acc[nt][1] = exp2f(acc[nt][1] * C2 - nm0);
            acc[nt][2] = exp2f(acc[nt][2] * C2 - nm1);
            acc[nt][3] = exp2f(acc[nt][3] * C2 - nm1);
            rs0 += acc[nt][0] + acc[nt][1];
            rs1 += acc[nt][2] + acc[nt][3];
        }
        rs0 += __shfl_xor_sync(0xffffffffu, rs0, 1);
        rs0 += __shfl_xor_sync(0xffffffffu, rs0, 2);
        rs1 += __shfl_xor_sync(0xffffffffu, rs1, 1);
        rs1 += __shfl_xor_sync(0xffffffffu, rs1, 2);
        lsum[0] = lsum[0] * sc0 + rs0;
        lsum[1] = lsum[1] * sc1 + rs1;

#pragma unroll
        for (int i = 0; i < 8; i++) {
            out[i][0] *= sc0; out[i][1] *= sc0;
            out[i][2] *= sc1; out[i][3] *= sc1;
        }

#pragma unroll
        for (int s = 0; s < 8; s++) {
            uint32_t aPh[4], aPl[4];
            aPh[0] = packh_hi(acc[2*s][0],   acc[2*s][1]);
            aPh[1] = packh_hi(acc[2*s][2],   acc[2*s][3]);
            aPh[2] = packh_hi(acc[2*s+1][0], acc[2*s+1][1]);
            aPh[3] = packh_hi(acc[2*s+1][2], acc[2*s+1][3]);
            aPl[0] = packh_lo(acc[2*s][0],   acc[2*s][1],   aPh[0]);
            aPl[1] = packh_lo(acc[2*s][2],   acc[2*s][3],   aPh[1]);
            aPl[2] = packh_lo(acc[2*s+1][0], acc[2*s+1][1], aPh[2]);
            aPl[3] = packh_lo(acc[2*s+1][2], acc[2*s+1][3], aPh[3]);

#pragma unroll
            for (int g = 0; g < 4; g++) {
                uint32_t off = (s * 16 + v_krel) * FROWB + (g * 16 + v_chi) * 2;
                uint32_t vh4[4];
                ldsm4t(vh4, sV + off);
                mma_h(out[2*g],   aPh, vh4);
                mma_h(out[2*g+1], aPh, vh4 + 2);
                mma_h(out[2*g],   aPl, vh4);
                mma_h(out[2*g+1], aPl, vh4 + 2);
            }
        }
        __syncthreads();
    }

    float inv0 = 1.0f / lsum[0];
    float inv1 = 1.0f / lsum[1];
    size_t gr0 = (qrow0 + wid * 16 + (lane >> 2)) * DIM;
    size_t gr1 = gr0 + 8 * DIM;
#pragma unroll
    for (int nt = 0; nt < 8; nt++) {
        int col = hc + nt * 8 + (lane & 3) * 2;
        float f0 = out[nt][0] * inv0, f1 = out[nt][1] * inv0;
        float f2 = out[nt][2] * inv1, f3 = out[nt][3] * inv1;
        uint32_t h0 = packh_hi(f0, f1);
        uint32_t h1 = packh_hi(f2, f3);
        *(uint32_t*)&Oh[gr0 + col] = h0;
        *(uint32_t*)&Ol[gr0 + col] = packh_lo(f0, f1, h0);
        *(uint32_t*)&Oh[gr1 + col] = h1;
        *(uint32_t*)&Ol[gr1 + col] = packh_lo(f2, f3, h1);
    }
}

// ---------------------------------------------------------------------------
// Launch
// ---------------------------------------------------------------------------
extern "C" void kernel_launch(void* const* d_in, const int* in_sizes, int n_in,
                              void* d_out, int out_size)
{
    const float* x  = (const float*)d_in[0];
    const float* Wq = (const float*)d_in[1];
    const float* Wk = (const float*)d_in[2];
    const float* Wv = (const float*)d_in[3];
    const float* Wo = (const float*)d_in[4];
    const float* bo = (const float*)d_in[5];
    float* out = (float*)d_out;

    ush *xh, *xl, *qh, *ql, *kh, *vh, *ah, *al;
    ush *wqh, *wkh, *wvh, *woh;
    cudaGetSymbolAddress((void**)&xh, g_xh);
    cudaGetSymbolAddress((void**)&xl, g_xl);
    cudaGetSymbolAddress((void**)&qh, g_qh);
    cudaGetSymbolAddress((void**)&ql, g_ql);
    cudaGetSymbolAddress((void**)&kh, g_kh);
    cudaGetSymbolAddress((void**)&vh, g_vh);
    cudaGetSymbolAddress((void**)&ah, g_ah);
    cudaGetSymbolAddress((void**)&al, g_al);
    cudaGetSymbolAddress((void**)&wqh, g_wqh);
    cudaGetSymbolAddress((void**)&wkh, g_wkh);
    cudaGetSymbolAddress((void**)&wvh, g_wvh);
    cudaGetSymbolAddress((void**)&woh, g_woh);

    cudaFuncSetAttribute(gemm_fused<1>, cudaFuncAttributeMaxDynamicSharedMemorySize, GEMM_SMEM);
    cudaFuncSetAttribute(gemm_fused<3>, cudaFuncAttributeMaxDynamicSharedMemorySize, GEMM_SMEM);
    cudaFuncSetAttribute(flash_mma, cudaFuncAttributeMaxDynamicSharedMemorySize, FLASH_SMEM);

    int total4 = N4X + 4 * N4W;
    split_all<<<(total4 + 255) / 256, 256>>>(x, Wq, Wk, Wv, Wo,
                                             xh, xl, wqh, wkh, wvh, woh);

    // Fused QKV projection + RoPE epilogue: 24x32 = 768 CTAs
    gemm_fused<3><<<dim3(3 * DIM / GBN, MTOT / GBM), GNT, GEMM_SMEM>>>(
        xh, xl, wqh, wkh, wvh,
        nullptr, nullptr, qh, ql, kh, vh);

    flash_mma<<<dim3(SEQ / 64, NH, BSZ), FNT, FLASH_SMEM>>>(qh, ql, kh, vh, ah, al);

    // O projection + bias: 8x32 = 256 CTAs  (captured by ncu at launch idx 3)
    gemm_fused<1><<<dim3(DIM / GBN, MTOT / GBM), GNT, GEMM_SMEM>>>(
        ah, al, woh, nullptr, nullptr,
        bo, out, nullptr, nullptr, nullptr, nullptr);
}

// round 16
// speedup vs baseline: 1.0981x; 1.0981x over previous
#include <cuda_runtime.h>
#include <cuda_bf16.h>
#include <cuda_fp16.h>
#include <math.h>
#include <stdint.h>

#define DIM 1024
#define BSZ 4
#define SEQ 1024
#define NH 16
#define HD 64
#define MTOT (BSZ*SEQ)

typedef unsigned short ush;

// ---------------------------------------------------------------------------
// Scratch (device globals, no allocations).  All fp16.
// ---------------------------------------------------------------------------
__device__ ush g_xh[MTOT*DIM], g_xl[MTOT*DIM];     // x split
__device__ ush g_qh[MTOT*DIM], g_ql[MTOT*DIM];     // Q split (rotated)
__device__ ush g_kh[MTOT*DIM];                     // K fp16 (rotated)
__device__ ush g_vh[MTOT*DIM];                     // V fp16
__device__ ush g_ah[MTOT*DIM], g_al[MTOT*DIM];     // attn-out split
__device__ ush g_wqh[DIM*DIM];                     // weights fp16 (hi only)
__device__ ush g_wkh[DIM*DIM];
__device__ ush g_wvh[DIM*DIM];
__device__ ush g_woh[DIM*DIM];

// ---------------------------------------------------------------------------
// Helpers
// ---------------------------------------------------------------------------
__device__ __forceinline__ uint32_t smem_u32(const void* p) {
    uint32_t a;
    asm("{ .reg .u64 t; cvta.to.shared.u64 t, %1; cvt.u32.u64 %0, t; }" : "=r"(a) : "l"(p));
    return a;
}

__device__ __forceinline__ void ldsm4(uint32_t* r, uint32_t addr) {
    asm volatile("ldmatrix.sync.aligned.m8n8.x4.shared.b16 {%0,%1,%2,%3}, [%4];"
                 : "=r"(r[0]), "=r"(r[1]), "=r"(r[2]), "=r"(r[3]) : "r"(addr));
}
__device__ __forceinline__ void ldsm4t(uint32_t* r, uint32_t addr) {
    asm volatile("ldmatrix.sync.aligned.m8n8.x4.trans.shared.b16 {%0,%1,%2,%3}, [%4];"
                 : "=r"(r[0]), "=r"(r[1]), "=r"(r[2]), "=r"(r[3]) : "r"(addr));
}

// fp16 in, f32 accum
__device__ __forceinline__ void mma_h(float* c, const uint32_t* a, const uint32_t* b) {
    asm volatile(
        "mma.sync.aligned.m16n8k16.row.col.f32.f16.f16.f32 "
        "{%0,%1,%2,%3}, {%4,%5,%6,%7}, {%8,%9}, {%0,%1,%2,%3};\n"
        : "+f"(c[0]), "+f"(c[1]), "+f"(c[2]), "+f"(c[3])
        : "r"(a[0]), "r"(a[1]), "r"(a[2]), "r"(a[3]), "r"(b[0]), "r"(b[1]));
}

__device__ __forceinline__ void cp16(uint32_t saddr, const void* g) {
    asm volatile("cp.async.cg.shared.global [%0], [%1], 16;" :: "r"(saddr), "l"(g));
}
#define CP_COMMIT() asm volatile("cp.async.commit_group;" ::: "memory")
#define CP_WAIT(n)  asm volatile("cp.async.wait_group %0;" :: "n"(n) : "memory")

// fp16 packers
__device__ __forceinline__ uint32_t packh_hi(float c0, float c1) {
    __half2 h = __floats2half2_rn(c0, c1);
    return *(uint32_t*)&h;
}
__device__ __forceinline__ uint32_t packh_lo(float c0, float c1, uint32_t hibits) {
    __half2 h = *(__half2*)&hibits;
    __half2 r = __floats2half2_rn(c0 - __half2float(__low2half(h)),
                                  c1 - __half2float(__high2half(h)));
    return *(uint32_t*)&r;
}

// ---------------------------------------------------------------------------
// Merged split kernel: x -> fp16 (hi,lo); weights -> fp16 hi only
// ---------------------------------------------------------------------------
#define N4X (MTOT*DIM/4)
#define N4W (DIM*DIM/4)

__global__ void split_all(const float* __restrict__ x,
                          const float* __restrict__ wq, const float* __restrict__ wk,
                          const float* __restrict__ wv, const float* __restrict__ wo,
                          ush* __restrict__ xh, ush* __restrict__ xl,
                          ush* __restrict__ wqh, ush* __restrict__ wkh,
                          ush* __restrict__ wvh, ush* __restrict__ woh)
{
    int i = blockIdx.x * blockDim.x + threadIdx.x;
    const float* src; ush* hi; ush* lo = nullptr; int j;
    if (i < N4X)            { src = x;  hi = xh;  lo = xl; j = i; }
    else if (i < N4X+N4W)   { src = wq; hi = wqh; j = i - N4X; }
    else if (i < N4X+2*N4W) { src = wk; hi = wkh; j = i - N4X - N4W; }
    else if (i < N4X+3*N4W) { src = wv; hi = wvh; j = i - N4X - 2*N4W; }
    else if (i < N4X+4*N4W) { src = wo; hi = woh; j = i - N4X - 3*N4W; }
    else return;

    float4 v = ((const float4*)src)[j];
    float vv[4] = {v.x, v.y, v.z, v.w};
    ush h[4];
#pragma unroll
    for (int q = 0; q < 4; q++) h[q] = __half_as_ushort(__float2half_rn(vv[q]));
    ((uint2*)hi)[j] = make_uint2((uint32_t)h[0] | ((uint32_t)h[1] << 16),
                                 (uint32_t)h[2] | ((uint32_t)h[3] << 16));
    if (lo) {
        ush l[4];
#pragma unroll
        for (int q = 0; q < 4; q++)
            l[q] = __half_as_ushort(__float2half_rn(vv[q] - __half2float(__ushort_as_half(h[q]))));
        ((uint2*)lo)[j] = make_uint2((uint32_t)l[0] | ((uint32_t)l[1] << 16),
                                     (uint32_t)l[2] | ((uint32_t)l[3] << 16));
    }
}

// ---------------------------------------------------------------------------
// HMMA GEMM (R13 config, best known): CTA 128x128, BK=64, 256 thr / 8 warps
// (4x2), warp tile 32x64, 2 CTAs/SM. Independent-accumulator MMA ordering.
// OUTMODE 1: fp32+bias (O).  OUTMODE 3: fused QKV epilogue.
// ---------------------------------------------------------------------------
#define GBM 128
#define GBN 128
#define GBK 64
#define GST 72                        // smem row stride (elems) = 144 B
#define TBUF (128*GST*2)              // 18432 B
#define GSTG (3*TBUF)                 // Ah, Al, Bh = 55296 B
#define GEMM_SMEM (2*GSTG)            // 110592 B -> 2 CTAs/SM
#define GNKB (DIM/GBK)                // 16

template<int OUTMODE>
__global__ void __launch_bounds__(256, 2)
gemm_fused(const ush* __restrict__ Ah, const ush* __restrict__ Al,
           const ush* __restrict__ B0h, const ush* __restrict__ B1h,
           const ush* __restrict__ B2h,
           const float* __restrict__ bias, float* __restrict__ C,
           ush* __restrict__ Qh_, ush* __restrict__ Ql_,
           ush* __restrict__ Kh_, ush* __restrict__ Vh_)
{
    extern __shared__ char smc[];
    uint32_t sbase = smem_u32(smc);
    int tid  = threadIdx.x;
    int wid  = tid >> 5, lane = tid & 31;
    int wm   = wid >> 1;               // 0..3  (32-row slice)
    int wn   = wid & 1;                // 0..1  (64-col half)
    int m0   = blockIdx.y * GBM;
    int n0g  = blockIdx.x * GBN;

    const ush* gBh;
    if (OUTMODE == 3) {
        int mat  = n0g >> 10;
        int nloc = n0g & 1023;
        gBh = (mat == 0 ? B0h : mat == 1 ? B1h : B2h) + (size_t)nloc * DIM;
    } else {
        gBh = B0h + (size_t)n0g * DIM;
    }
    const ush* gAh = Ah + (size_t)m0 * DIM;
    const ush* gAl = Al + (size_t)m0 * DIM;

    auto load_stage = [&](int p, int kb) {
        uint32_t sb = sbase + p * GSTG;
        // 128 rows x 8 chunks(16B) = 1024 chunks per matrix, 4 per thread
#pragma unroll
        for (int r = 0; r < 4; r++) {
            int c = tid + 256 * r;
            int row = c >> 3, ch = c & 7;
            uint32_t so = (uint32_t)(row * GST + ch * 8) * 2;
            size_t go = (size_t)row * DIM + kb * GBK + ch * 8;
            cp16(sb + so,            gAh + go);
            cp16(sb + TBUF + so,     gAl + go);
            cp16(sb + 2 * TBUF + so, gBh + go);
        }
    };

    float acc[2][8][4];
#pragma unroll
    for (int i = 0; i < 2; i++)
#pragma unroll
        for (int j = 0; j < 8; j++)
#pragma unroll
            for (int q = 0; q < 4; q++) acc[i][j][q] = 0.0f;

    int a_row_lane = lane & 15;
    int a_hi8      = lane >> 4;
    int b_row_lane = (lane & 7) + ((lane & 16) ? 8 : 0);
    int b_hi8      = (lane >> 3) & 1;

    load_stage(0, 0); CP_COMMIT();

    for (int kb = 0; kb < GNKB; kb++) {
        if (kb + 1 < GNKB) { load_stage((kb + 1) & 1, kb + 1); CP_COMMIT(); CP_WAIT(1); }
        else CP_WAIT(0);
        __syncthreads();

        uint32_t sb  = sbase + (kb & 1) * GSTG;
        uint32_t sAh = sb, sAl = sb + TBUF, sBh = sb + 2 * TBUF;

#pragma unroll
        for (int ks = 0; ks < 4; ks++) {
            uint32_t aH[2][4], aL[2][4], b4[4][4];
#pragma unroll
            for (int mt = 0; mt < 2; mt++) {
                int row = wm * 32 + mt * 16 + a_row_lane;
                uint32_t off = (uint32_t)(row * GST + ks * 16 + a_hi8 * 8) * 2;
                ldsm4(aH[mt], sAh + off);
                ldsm4(aL[mt], sAl + off);
            }
#pragma unroll
            for (int ng = 0; ng < 4; ng++) {
                int row = wn * 64 + ng * 16 + b_row_lane;
                uint32_t off = (uint32_t)(row * GST + ks * 16 + b_hi8 * 8) * 2;
                ldsm4(b4[ng], sBh + off);
            }
            // pass H: 16 consecutive MMAs on distinct accumulators
#pragma unroll
            for (int ng = 0; ng < 4; ng++)
#pragma unroll
                for (int mt = 0; mt < 2; mt++) {
                    mma_h(acc[mt][2*ng],   aH[mt], b4[ng]);
                    mma_h(acc[mt][2*ng+1], aH[mt], b4[ng] + 2);
                }
            // pass L
#pragma unroll
            for (int ng = 0; ng < 4; ng++)
#pragma unroll
                for (int mt = 0; mt < 2; mt++) {
                    mma_h(acc[mt][2*ng],   aL[mt], b4[ng]);
                    mma_h(acc[mt][2*ng+1], aL[mt], b4[ng] + 2);
                }
        }
        __syncthreads();
    }

    // ---- epilogue ----
#pragma unroll
    for (int mt = 0; mt < 2; mt++) {
        int row = m0 + wm * 32 + mt * 16 + (lane >> 2);
#pragma unroll
        for (int nt = 0; nt < 8; nt++) {
            int col = n0g + wn * 64 + nt * 8 + (lane & 3) * 2;
            float2 v0 = make_float2(acc[mt][nt][0], acc[mt][nt][1]);
            float2 v1 = make_float2(acc[mt][nt][2], acc[mt][nt][3]);
            if (OUTMODE == 1) {
                v0.x += bias[col]; v0.y += bias[col + 1];
                v1.x += bias[col]; v1.y += bias[col + 1];
                *(float2*)&C[(size_t)row * DIM + col] = v0;
                *(float2*)&C[(size_t)(row + 8) * DIM + col] = v1;
            } else {
                int mat  = col >> 10;
                int nloc = col & 1023;
                size_t d0 = (size_t)row * DIM + nloc;
                size_t d1 = d0 + (size_t)8 * DIM;
                if (mat == 2) {
                    *(uint32_t*)&Vh_[d0] = packh_hi(v0.x, v0.y);
                    *(uint32_t*)&Vh_[d1] = packh_hi(v1.x, v1.y);
                } else {
                    int s = row & (SEQ - 1);
                    float ex = (float)nloc * (1.0f / (float)DIM);
                    float freq = powf(10000.0f, -ex);
                    float sn0, cs0, sn1, cs1;
                    sincosf((float)s * freq, &sn0, &cs0);
                    sincosf((float)(s + 8) * freq, &sn1, &cs1);
                    float r0x = v0.x * cs0 - v0.y * sn0;
                    float r0y = v0.x * sn0 + v0.y * cs0;
                    float r1x = v1.x * cs1 - v1.y * sn1;
                    float r1y = v1.x * sn1 + v1.y * cs1;
                    if (mat == 0) {
                        uint32_t h0 = packh_hi(r0x, r0y);
                        uint32_t h1 = packh_hi(r1x, r1y);
                        *(uint32_t*)&Qh_[d0] = h0;
                        *(uint32_t*)&Ql_[d0] = packh_lo(r0x, r0y, h0);
                        *(uint32_t*)&Qh_[d1] = h1;
                        *(uint32_t*)&Ql_[d1] = packh_lo(r1x, r1y, h1);
                    } else {
                        *(uint32_t*)&Kh_[d0] = packh_hi(r0x, r0y);
                        *(uint32_t*)&Kh_[d1] = packh_hi(r1x, r1y);
                    }
                }
            }
        }
    }
}

// ---------------------------------------------------------------------------
// Flash attention, fp16 2-pass. 64 q-rows/CTA, 128 threads / 4 warps,
// key tiles of 128, 2 CTAs/SM. P·V reordered: batch V-ldsm, H pass, L pass.
// ---------------------------------------------------------------------------
#define FROWB 144
#define FQT (64*FROWB)
#define FKT (128*FROWB)
#define FKV0 (2*FQT)
#define FSTG (2*FKT)
#define FLASH_SMEM (2*FQT + 2*FSTG)
#define NKT (SEQ/128)
#define FNT 128

__global__ void __launch_bounds__(FNT, 2)
flash_mma(const ush* __restrict__ Qh, const ush* __restrict__ Ql,
          const ush* __restrict__ Kh, const ush* __restrict__ Vh,
          ush* __restrict__ Oh, ush* __restrict__ Ol)
{
    extern __shared__ char smf[];
    uint32_t sbase = smem_u32(smf);
    int tid = threadIdx.x;
    int wid = tid >> 5, lane = tid & 31;
    int b = blockIdx.z, h = blockIdx.y;
    int q0 = blockIdx.x * 64;

    size_t qrow0 = (size_t)(b * SEQ + q0);
    size_t krow0 = (size_t)(b * SEQ);
    int hc = h * HD;

    {
#pragma unroll
        for (int i = 0; i < 4; i++) {
            int c = tid + i * FNT;
            int row = c >> 3, ch = c & 7;
            uint32_t so = sbase + row * FROWB + ch * 16;
            size_t go = (qrow0 + row) * DIM + hc + ch * 8;
            cp16(so, Qh + go);
            cp16(so + FQT, Ql + go);
        }
        CP_COMMIT();
    }

    auto load_kv = [&](int t) {
        uint32_t sb = sbase + FKV0 + (t & 1) * FSTG;
        size_t rbase = (krow0 + (size_t)t * 128) * DIM + hc;
#pragma unroll
        for (int i = 0; i < 8; i++) {
            int c = tid + i * FNT;
            int row = c >> 3, ch = c & 7;
            uint32_t so = sb + row * FROWB + ch * 16;
            size_t go = rbase + (size_t)row * DIM + ch * 8;
            cp16(so,       Kh + go);
            cp16(so + FKT, Vh + go);
        }
        CP_COMMIT();
    };

    load_kv(0);

    float out[8][4];
#pragma unroll
    for (int i = 0; i < 8; i++)
#pragma unroll
        for (int j = 0; j < 4; j++) out[i][j] = 0.0f;
    float m2[2] = {-1e30f, -1e30f};
    float lsum[2] = {0.0f, 0.0f};

    uint32_t aQh[4][4], aQl[4][4];
    const float C2 = 0.18033688f;

    int a_row_lane = lane & 15;
    int a_hi8      = lane >> 4;
    int b_row_lane = (lane & 7) + ((lane & 16) ? 8 : 0);
    int b_hi8      = (lane >> 3) & 1;
    int v_krel = (lane & 7) + ((lane & 8) ? 8 : 0);
    int v_chi  = (lane & 16) ? 8 : 0;

    for (int t = 0; t < NKT; t++) {
        if (t + 1 < NKT) { load_kv(t + 1); CP_WAIT(1); }
        else CP_WAIT(0);
        __syncthreads();

        if (t == 0) {
#pragma unroll
            for (int kk = 0; kk < 4; kk++) {
                int row = wid * 16 + a_row_lane;
                uint32_t off = sbase + row * FROWB + (kk * 16 + a_hi8 * 8) * 2;
                ldsm4(aQh[kk], off);
                ldsm4(aQl[kk], off + FQT);
            }
        }

        uint32_t sK = sbase + FKV0 + (t & 1) * FSTG;
        uint32_t sV = sK + FKT;

        float acc[16][4];
#pragma unroll
        for (int i = 0; i < 16; i++)
#pragma unroll
            for (int j = 0; j < 4; j++) acc[i][j] = 0.0f;

#pragma unroll
        for (int kk = 0; kk < 4; kk++) {
#pragma unroll
            for (int ntp = 0; ntp < 8; ntp++) {
                int row = ntp * 16 + b_row_lane;
                uint32_t off = row * FROWB + (kk * 16 + b_hi8 * 8) * 2;
                uint32_t bh4[4];
                ldsm4(bh4, sK + off);
                mma_h(acc[2*ntp],   aQh[kk], bh4);
                mma_h(acc[2*ntp+1], aQh[kk], bh4 + 2);
                mma_h(acc[2*ntp],   aQl[kk], bh4);
                mma_h(acc[2*ntp+1], aQl[kk], bh4 + 2);
            }
        }

        float lm0 = -1e30f, lm1 = -1e30f;
#pragma unroll
        for (int nt = 0; nt < 16; nt++) {
            lm0 = fmaxf(lm0, fmaxf(acc[nt][0], acc[nt][1]));
            lm1 = fmaxf(lm1, fmaxf(acc[nt][2], acc[nt][3]));
        }
        lm0 = fmaxf(lm0, __shfl_xor_sync(0xffffffffu, lm0, 1));
        lm0 = fmaxf(lm0, __shfl_xor_sync(0xffffffffu, lm0, 2));
        lm1 = fmaxf(lm1, __shfl_xor_sync(0xffffffffu, lm1, 1));
        lm1 = fmaxf(lm1, __shfl_xor_sync(0xffffffffu, lm1, 2));
        float nm0 = fmaxf(m2[0], lm0 * C2);
        float nm1 = fmaxf(m2[1], lm1 * C2);
        float sc0 = exp2f(m2[0] - nm0);
        float sc1 = exp2f(m2[1] - nm1);
        m2[0] = nm0; m2[1] = nm1;

        float rs0 = 0.0f, rs1 = 0.0f;
#pragma unroll
        for (int nt = 0; nt < 16; nt++) {
            acc[nt][0] = exp2f(acc[nt][0] * C2 - nm0);
            acc[nt][1] = exp2f(acc[nt][1] * C2 - nm0);
            acc[nt][2] = exp2f(acc[nt][2] * C2 - nm1);
            acc[nt][3] = exp2f(acc[nt][3] * C2 - nm1);
            rs0 += acc[nt][0] + acc[nt][1];
            rs1 += acc[nt][2] + acc[nt][3];
        }
        rs0 += __shfl_xor_sync(0xffffffffu, rs0, 1);
        rs0 += __shfl_xor_sync(0xffffffffu, rs0, 2);
        rs1 += __shfl_xor_sync(0xffffffffu, rs1, 1);
        rs1 += __shfl_xor_sync(0xffffffffu, rs1, 2);
        lsum[0] = lsum[0] * sc0 + rs0;
        lsum[1] = lsum[1] * sc1 + rs1;

#pragma unroll
        for (int i = 0; i < 8; i++) {
            out[i][0] *= sc0; out[i][1] *= sc0;
            out[i][2] *= sc1; out[i][3] *= sc1;
        }

        // ---- P · V: batch V ldsm, then H pass, then L pass ----
#pragma unroll
        for (int s = 0; s < 8; s++) {
            uint32_t aPh[4], aPl[4];
            aPh[0] = packh_hi(acc[2*s][0],   acc[2*s][1]);
            aPh[1] = packh_hi(acc[2*s][2],   acc[2*s][3]);
            aPh[2] = packh_hi(acc[2*s+1][0], acc[2*s+1][1]);
            aPh[3] = packh_hi(acc[2*s+1][2], acc[2*s+1][3]);
            aPl[0] = packh_lo(acc[2*s][0],   acc[2*s][1],   aPh[0]);
            aPl[1] = packh_lo(acc[2*s][2],   acc[2*s][3],   aPh[1]);
            aPl[2] = packh_lo(acc[2*s+1][0], acc[2*s+1][1], aPh[2]);
            aPl[3] = packh_lo(acc[2*s+1][2], acc[2*s+1][3], aPh[3]);

            uint32_t v4[4][4];
#pragma unroll
            for (int g = 0; g < 4; g++) {
                uint32_t off = (s * 16 + v_krel) * FROWB + (g * 16 + v_chi) * 2;
                ldsm4t(v4[g], sV + off);
            }
            // H pass: 8 independent accumulators
#pragma unroll
            for (int g = 0; g < 4; g++) {
                mma_h(out[2*g],   aPh, v4[g]);
                mma_h(out[2*g+1], aPh, v4[g] + 2);
            }
            // L pass
#pragma unroll
            for (int g = 0; g < 4; g++) {
                mma_h(out[2*g],   aPl, v4[g]);
                mma_h(out[2*g+1], aPl, v4[g] + 2);
            }
        }
        __syncthreads();
    }

    float inv0 = 1.0f / lsum[0];
    float inv1 = 1.0f / lsum[1];
    size_t gr0 = (qrow0 + wid * 16 + (lane >> 2)) * DIM;
    size_t gr1 = gr0 + 8 * DIM;
#pragma unroll
    for (int nt = 0; nt < 8; nt++) {
        int col = hc + nt * 8 + (lane & 3) * 2;
        float f0 = out[nt][0] * inv0, f1 = out[nt][1] * inv0;
        float f2 = out[nt][2] * inv1, f3 = out[nt][3] * inv1;
        uint32_t h0 = packh_hi(f0, f1);
        uint32_t h1 = packh_hi(f2, f3);
        *(uint32_t*)&Oh[gr0 + col] = h0;
        *(uint32_t*)&Ol[gr0 + col] = packh_lo(f0, f1, h0);
        *(uint32_t*)&Oh[gr1 + col] = h1;
        *(uint32_t*)&Ol[gr1 + col] = packh_lo(f2, f3, h1);
    }
}

// ---------------------------------------------------------------------------
// Launch
// ---------------------------------------------------------------------------
extern "C" void kernel_launch(void* const* d_in, const int* in_sizes, int n_in,
                              void* d_out, int out_size)
{
    const float* x  = (const float*)d_in[0];
    const float* Wq = (const float*)d_in[1];
    const float* Wk = (const float*)d_in[2];
    const float* Wv = (const float*)d_in[3];
    const float* Wo = (const float*)d_in[4];
    const float* bo = (const float*)d_in[5];
    float* out = (float*)d_out;

    ush *xh, *xl, *qh, *ql, *kh, *vh, *ah, *al;
    ush *wqh, *wkh, *wvh, *woh;
    cudaGetSymbolAddress((void**)&xh, g_xh);
    cudaGetSymbolAddress((void**)&xl, g_xl);
    cudaGetSymbolAddress((void**)&qh, g_qh);
    cudaGetSymbolAddress((void**)&ql, g_ql);
    cudaGetSymbolAddress((void**)&kh, g_kh);
    cudaGetSymbolAddress((void**)&vh, g_vh);
    cudaGetSymbolAddress((void**)&ah, g_ah);
    cudaGetSymbolAddress((void**)&al, g_al);
    cudaGetSymbolAddress((void**)&wqh, g_wqh);
    cudaGetSymbolAddress((void**)&wkh, g_wkh);
    cudaGetSymbolAddress((void**)&wvh, g_wvh);
    cudaGetSymbolAddress((void**)&woh, g_woh);

    cudaFuncSetAttribute(gemm_fused<1>, cudaFuncAttributeMaxDynamicSharedMemorySize, GEMM_SMEM);
    cudaFuncSetAttribute(gemm_fused<3>, cudaFuncAttributeMaxDynamicSharedMemorySize, GEMM_SMEM);
    cudaFuncSetAttribute(flash_mma, cudaFuncAttributeMaxDynamicSharedMemorySize, FLASH_SMEM);

    int total4 = N4X + 4 * N4W;
    split_all<<<(total4 + 255) / 256, 256>>>(x, Wq, Wk, Wv, Wo,
                                             xh, xl, wqh, wkh, wvh, woh);

    // Fused QKV projection + RoPE epilogue: 24x32 = 768 CTAs
    gemm_fused<3><<<dim3(3 * DIM / GBN, MTOT / GBM), 256, GEMM_SMEM>>>(
        xh, xl, wqh, wkh, wvh,
        nullptr, nullptr, qh, ql, kh, vh);

    flash_mma<<<dim3(SEQ / 64, NH, BSZ), FNT, FLASH_SMEM>>>(qh, ql, kh, vh, ah, al);

    // O projection + bias: 8x32 = 256 CTAs  (captured by ncu at launch idx 3)
    gemm_fused<1><<<dim3(DIM / GBN, MTOT / GBM), 256, GEMM_SMEM>>>(
        ah, al, woh, nullptr, nullptr,
        bo, out, nullptr, nullptr, nullptr, nullptr);
}